// round 7
// baseline (speedup 1.0000x reference)
#include <cuda_runtime.h>
#include <cstdint>

#define NN 8192
#define CC 256
#define TOPK 17
#define KNN 16

// ---------------- scratch (device globals: allocation-free) ----------------
__device__ float g_h[NN * CC];                      // 8 MB
__device__ unsigned long long g_topk[NN * TOPK];    // ~1.1 MB
__device__ float g_sum;

// ------ Eigen/MLIR fast-tanh, FMA variant (clamp 7.99881172180175781) ------
// Exact replica of the mlir math-polynomial-approximation / Eigen ptanh_float
// FMA path that XLA:CPU emits: clamp, x2, two Horner FMA chains, IEEE divide,
// |x| < 0.0004 passthrough. Bit-identical for bit-identical input.
// (Resubmission: R6 failed with cudaErrorSystemNotReady — infra, kernel never ran.)
__device__ __forceinline__ float ftanh(float x) {
    const float kMax = 7.99881172180175781f;
    float xc = fminf(fmaxf(x, -kMax), kMax);
    float x2 = __fmul_rn(xc, xc);
    float p = __fmaf_rn(x2, -2.76076847742355e-16f, 2.00018790482477e-13f);
    p = __fmaf_rn(x2, p, -8.60467152213735e-11f);
    p = __fmaf_rn(x2, p,  5.12229709037114e-08f);
    p = __fmaf_rn(x2, p,  1.48572235717979e-05f);
    p = __fmaf_rn(x2, p,  6.37261928875436e-04f);
    p = __fmaf_rn(x2, p,  4.89352455891786e-03f);
    p = __fmul_rn(xc, p);
    float q = __fmaf_rn(x2, 1.19825839466702e-06f, 1.18534705686654e-04f);
    q = __fmaf_rn(x2, q, 2.26843463243900e-03f);
    q = __fmaf_rn(x2, q, 4.89352518554385e-03f);
    float r = __fdiv_rn(p, q);
    return (fabsf(x) < 0.0004f) ? x : r;
}

// ---------------- K1: h = x @ lin  (M=8192, N=256, K=256) -------------------
__global__ void __launch_bounds__(256) k1_gemm(const float* __restrict__ x,
                                               const float* __restrict__ lin) {
    __shared__ float As[16][64];   // As[k][m]
    __shared__ float Bs[16][64];   // Bs[k][n]
    int bm = blockIdx.x, bn = blockIdx.y;
    int tid = threadIdx.x;
    int tx = tid & 15, ty = tid >> 4;
    int ar = tid >> 2, ak = (tid & 3) * 4;    // A load: row, k-base
    int bk = tid >> 4, bc = (tid & 15) * 4;   // B load: k, col-base

    float acc[4][4];
#pragma unroll
    for (int i = 0; i < 4; i++)
#pragma unroll
        for (int j = 0; j < 4; j++) acc[i][j] = 0.f;

    for (int kt = 0; kt < CC; kt += 16) {
        float4 av = *(const float4*)(x + (size_t)(bm * 64 + ar) * CC + kt + ak);
        float4 bv = *(const float4*)(lin + (size_t)(kt + bk) * CC + bn * 64 + bc);
        __syncthreads();
        As[ak + 0][ar] = av.x; As[ak + 1][ar] = av.y;
        As[ak + 2][ar] = av.z; As[ak + 3][ar] = av.w;
        *(float4*)&Bs[bk][bc] = bv;
        __syncthreads();
#pragma unroll
        for (int kk = 0; kk < 16; kk++) {
            float a[4], b[4];
#pragma unroll
            for (int i = 0; i < 4; i++) a[i] = As[kk][ty * 4 + i];
#pragma unroll
            for (int j = 0; j < 4; j++) b[j] = Bs[kk][tx * 4 + j];
#pragma unroll
            for (int i = 0; i < 4; i++)
#pragma unroll
                for (int j = 0; j < 4; j++) acc[i][j] = __fmaf_rn(a[i], b[j], acc[i][j]);
        }
    }
#pragma unroll
    for (int i = 0; i < 4; i++) {
        float4 o = make_float4(acc[i][0], acc[i][1], acc[i][2], acc[i][3]);
        *(float4*)(g_h + (size_t)(bm * 64 + ty * 4 + i) * CC + bn * 64 + tx * 4) = o;
    }
}

// ------- K2: A = relu(ftanh(h h^T)); symmetric — upper tiles only -----------
__global__ void __launch_bounds__(256) k2_syrk(float* __restrict__ A) {
    __shared__ float As[8][128];
    __shared__ float Bs[8][128];
    int t = blockIdx.x, bi = 0;
    while (t >= 64 - bi) { t -= 64 - bi; ++bi; }
    int bj = bi + t;

    int tid = threadIdx.x;
    int tx = tid & 15, ty = tid >> 4;
    int lr = tid >> 1, lk = (tid & 1) * 4;
    const float* ap = g_h + (size_t)(bi * 128 + lr) * CC + lk;
    const float* bp = g_h + (size_t)(bj * 128 + lr) * CC + lk;

    float acc[8][8];
#pragma unroll
    for (int i = 0; i < 8; i++)
#pragma unroll
        for (int j = 0; j < 8; j++) acc[i][j] = 0.f;

    for (int kt = 0; kt < CC; kt += 8) {
        float4 av = *(const float4*)(ap + kt);
        float4 bv = *(const float4*)(bp + kt);
        __syncthreads();
        As[lk + 0][lr] = av.x; As[lk + 1][lr] = av.y;
        As[lk + 2][lr] = av.z; As[lk + 3][lr] = av.w;
        Bs[lk + 0][lr] = bv.x; Bs[lk + 1][lr] = bv.y;
        Bs[lk + 2][lr] = bv.z; Bs[lk + 3][lr] = bv.w;
        __syncthreads();
#pragma unroll
        for (int kk = 0; kk < 8; kk++) {
            float a[8], b[8];
#pragma unroll
            for (int i = 0; i < 8; i++) a[i] = As[kk][ty * 8 + i];
#pragma unroll
            for (int j = 0; j < 8; j++) b[j] = Bs[kk][tx * 8 + j];
#pragma unroll
            for (int i = 0; i < 8; i++)
#pragma unroll
                for (int j = 0; j < 8; j++) acc[i][j] = __fmaf_rn(a[i], b[j], acc[i][j]);
        }
    }
    // fused activation: relu(ftanh(.)) — exact reference tanh replica
#pragma unroll
    for (int i = 0; i < 8; i++)
#pragma unroll
        for (int j = 0; j < 8; j++) acc[i][j] = fmaxf(ftanh(acc[i][j]), 0.0f);

    int r0 = bi * 128 + ty * 8, c0 = bj * 128 + tx * 8;
#pragma unroll
    for (int i = 0; i < 8; i++) {
        float* p = A + (size_t)(r0 + i) * NN + c0;
        *(float4*)p       = make_float4(acc[i][0], acc[i][1], acc[i][2], acc[i][3]);
        *(float4*)(p + 4) = make_float4(acc[i][4], acc[i][5], acc[i][6], acc[i][7]);
    }
    if (bi != bj) {
#pragma unroll
        for (int j = 0; j < 8; j++) {
            float* p = A + (size_t)(c0 + j) * NN + r0;
            *(float4*)p       = make_float4(acc[0][j], acc[1][j], acc[2][j], acc[3][j]);
            *(float4*)(p + 4) = make_float4(acc[4][j], acc[5][j], acc[6][j], acc[7][j]);
        }
    }
}

// ---------------- K3: per-row top-17, ties -> smaller index -----------------
__device__ __forceinline__ void tk_insert(unsigned long long (&loc)[TOPK],
                                          unsigned long long key) {
    if (key > loc[TOPK - 1]) {
        loc[TOPK - 1] = key;
#pragma unroll
        for (int q = TOPK - 1; q > 0; q--) {
            unsigned long long a = loc[q - 1], b = loc[q];
            if (b > a) { loc[q - 1] = b; loc[q] = a; }
        }
    }
}

__device__ __forceinline__ unsigned long long warpmax_u64(unsigned long long v) {
#pragma unroll
    for (int off = 16; off; off >>= 1) {
        unsigned long long o = __shfl_xor_sync(0xffffffffu, v, off);
        if (o > v) v = o;
    }
    return v;
}

__global__ void __launch_bounds__(256) k3_topk(const float* __restrict__ A) {
    int row = blockIdx.x;
    int tid = threadIdx.x;
    unsigned long long loc[TOPK];
#pragma unroll
    for (int q = 0; q < TOPK; q++) loc[q] = 0ull;

    const float4* rp = (const float4*)(A + (size_t)row * NN);
#pragma unroll
    for (int it = 0; it < NN / 4 / 256; it++) {
        int c4 = tid + it * 256;
        float4 v = rp[c4];
        int col = c4 * 4;
        tk_insert(loc, ((unsigned long long)__float_as_uint(v.x) << 32) | (0xFFFFFFFFu - (unsigned)(col + 0)));
        tk_insert(loc, ((unsigned long long)__float_as_uint(v.y) << 32) | (0xFFFFFFFFu - (unsigned)(col + 1)));
        tk_insert(loc, ((unsigned long long)__float_as_uint(v.z) << 32) | (0xFFFFFFFFu - (unsigned)(col + 2)));
        tk_insert(loc, ((unsigned long long)__float_as_uint(v.w) << 32) | (0xFFFFFFFFu - (unsigned)(col + 3)));
    }

    __shared__ unsigned long long wl[8][TOPK];
    int lane = tid & 31, wp = tid >> 5;
    for (int it = 0; it < TOPK; it++) {
        unsigned long long best = warpmax_u64(loc[0]);
        unsigned m = __ballot_sync(0xffffffffu, loc[0] == best);
        if (lane == (__ffs(m) - 1)) {
#pragma unroll
            for (int q = 0; q < TOPK - 1; q++) loc[q] = loc[q + 1];
            loc[TOPK - 1] = 0ull;
        }
        if (lane == 0) wl[wp][it] = best;
    }
    __syncthreads();
    if (wp == 0) {
        int p = 0;
        for (int it = 0; it < TOPK; it++) {
            unsigned long long cand = (lane < 8) ? wl[lane][p] : 0ull;
            unsigned long long best = warpmax_u64(cand);
            unsigned m = __ballot_sync(0xffffffffu, (cand == best) && (lane < 8));
            if (lane == (__ffs(m) - 1)) p++;
            if (lane == 0) g_topk[row * TOPK + it] = best;
        }
    }
}

// ---------------- K4: sum of selected non-diagonal values -------------------
__global__ void k4_zero_sum() { g_sum = 0.f; }

__global__ void __launch_bounds__(256) k4_sum() {
    int i = blockIdx.x * blockDim.x + threadIdx.x;
    int stride = gridDim.x * blockDim.x;
    float s = 0.f;
    for (int e = i; e < NN * TOPK; e += stride) {
        unsigned long long key = g_topk[e];
        int row = e / TOPK;
        unsigned col = 0xFFFFFFFFu - (unsigned)(key & 0xFFFFFFFFull);
        float v = __uint_as_float((unsigned)(key >> 32));
        if (col < NN && col != (unsigned)row) s += v;
    }
    __shared__ float sh[256];
    sh[threadIdx.x] = s;
    __syncthreads();
    for (int st = 128; st; st >>= 1) {
        if (threadIdx.x < st) sh[threadIdx.x] += sh[threadIdx.x + st];
        __syncthreads();
    }
    if (threadIdx.x == 0) atomicAdd(&g_sum, sh[0]);
}

// ---------------- K5: zero-fill output --------------------------------------
__global__ void __launch_bounds__(256) k5_zero(float4* __restrict__ out) {
    size_t i = (size_t)blockIdx.x * blockDim.x + threadIdx.x;
    size_t stride = (size_t)gridDim.x * blockDim.x;
    float4 z = make_float4(0.f, 0.f, 0.f, 0.f);
    for (; i < (size_t)NN * NN / 4; i += stride) out[i] = z;
}

// ---------------- K6: scatter selected entries / mean -----------------------
__global__ void __launch_bounds__(256) k6_scatter(float* __restrict__ out) {
    int row = blockIdx.x * 8 + (threadIdx.x >> 5);
    int lane = threadIdx.x & 31;
    float mean = g_sum / (float)(KNN * NN);
    if (lane < TOPK) {
        unsigned long long key = g_topk[row * TOPK + lane];
        unsigned col = 0xFFFFFFFFu - (unsigned)(key & 0xFFFFFFFFull);
        float v = __uint_as_float((unsigned)(key >> 32));
        if (col < NN && col != (unsigned)row)
            out[(size_t)row * NN + col] = __fdiv_rn(v, mean);
    }
}

// ---------------- launch ----------------------------------------------------
extern "C" void kernel_launch(void* const* d_in, const int* in_sizes, int n_in,
                              void* d_out, int out_size) {
    const float* x   = (const float*)d_in[0];
    const float* lin = (const float*)d_in[1];
    // defensive: x is the 8192x256 tensor, lin the 256x256 one
    if (n_in >= 2 && in_sizes[0] < in_sizes[1]) {
        const float* tmp = x; x = lin; lin = tmp;
    }
    float* out = (float*)d_out;

    k1_gemm<<<dim3(128, 4), 256>>>(x, lin);
    k2_syrk<<<2080, 256>>>(out);
    k3_topk<<<8192, 256>>>(out);
    k4_zero_sum<<<1, 1>>>();
    k4_sum<<<128, 256>>>();
    k5_zero<<<16384, 256>>>((float4*)out);
    k6_scatter<<<1024, 256>>>(out);
}